// round 15
// baseline (speedup 1.0000x reference)
#include <cuda_runtime.h>
#include <cuda_bf16.h>
#include <cstdint>

// Problem constants
#define B_    4
#define T_    1024
#define C_    512
#define V_    4096
#define H_    8
#define Q_    256
#define MFULL 4096
#define MREST 1024
#define MTOT  5120
#define ZHAT_ELEMS (B_*C_*T_)
#define COMB_SCALE 0.044194173824159216f

// ---- scratch ----
__device__ float g_hs[MFULL*C_];
__device__ float g_Xq[MFULL*C_];
__device__ float g_Xp[MFULL*H_];
__device__ float g_value[V_*C_];
__device__ float g_kh[V_*C_];
__device__ float g_Q[MTOT*C_];
__device__ __nv_bfloat16 g_Qh[MTOT*C_];
__device__ __nv_bfloat16 g_Kh[V_*C_];
__device__ __nv_bfloat16 g_logitsh[(size_t)MTOT*V_];
__device__ float g_qnorm[MTOT];
__device__ int   g_knmax_i;
__device__ int   g_idx[MTOT];
__device__ int   g_cnt[V_];

// =====================  mma / cp.async helpers  =====================
#define MMA_TF32(c, a, b0, b1) \
    asm volatile("mma.sync.aligned.m16n8k8.row.col.f32.tf32.tf32.f32 " \
        "{%0,%1,%2,%3}, {%4,%5,%6,%7}, {%8,%9}, {%0,%1,%2,%3};" \
        : "+f"((c)[0]), "+f"((c)[1]), "+f"((c)[2]), "+f"((c)[3]) \
        : "r"((a)[0]), "r"((a)[1]), "r"((a)[2]), "r"((a)[3]), "r"(b0), "r"(b1))

#define MMA_BF16(c, a, b0, b1) \
    asm volatile("mma.sync.aligned.m16n8k16.row.col.f32.bf16.bf16.f32 " \
        "{%0,%1,%2,%3}, {%4,%5,%6,%7}, {%8,%9}, {%0,%1,%2,%3};" \
        : "+f"((c)[0]), "+f"((c)[1]), "+f"((c)[2]), "+f"((c)[3]) \
        : "r"((a)[0]), "r"((a)[1]), "r"((a)[2]), "r"((a)[3]), "r"(b0), "r"(b1))

__device__ __forceinline__ void cp16(uint32_t dst, const void* src) {
    asm volatile("cp.async.cg.shared.global [%0], [%1], 16;" :: "r"(dst), "l"(src));
}
#define CP_COMMIT() asm volatile("cp.async.commit_group;" ::: "memory")
#define CP_WAIT1()  asm volatile("cp.async.wait_group 1;" ::: "memory")
#define CP_WAIT0()  asm volatile("cp.async.wait_group 0;" ::: "memory")

__device__ __forceinline__ uint32_t tf32_of(float x) {
    uint32_t r; asm("cvt.rna.tf32.f32 %0, %1;" : "=r"(r) : "f"(x)); return r;
}
__device__ __forceinline__ void split1(float x, uint32_t& h, uint32_t& l) {
    h = tf32_of(x);
    l = tf32_of(x - __uint_as_float(h));
}

// =====================  fused pre-pass: init + transpose + xp  =====================
// blocks 0..2047: transpose z (B,C,T) -> hs (B*T, C); block 0 also inits
// blocks 2048..2063: Xp[b,t,:] = z[b,:,t] @ Wp + bp  (read z directly)
__global__ __launch_bounds__(256) void k_pre(const float* __restrict__ z,
                                             const float* __restrict__ Wp,
                                             const float* __restrict__ bp) {
    const int blk = blockIdx.x;
    const int tid = threadIdx.x;
    if (blk < 2048) {
        __shared__ float tile[32][33];
        int b = blk >> 9, y = (blk >> 4) & 31, x = blk & 15;
        int c0 = x << 5, t0 = y << 5;
        int tx = tid & 31, ty = tid >> 5;
        if (blk == 0) {
            for (int i = tid; i < V_; i += 256) g_cnt[i] = 0;
            if (tid == 0) g_knmax_i = 0;
        }
#pragma unroll
        for (int j = 0; j < 4; j++)
            tile[ty + 8*j][tx] = z[(b*C_ + c0 + ty + 8*j)*T_ + t0 + tx];
        __syncthreads();
#pragma unroll
        for (int j = 0; j < 4; j++)
            g_hs[(b*T_ + t0 + ty + 8*j)*C_ + c0 + tx] = tile[tx][ty + 8*j];
    } else {
        int i = blk - 2048;                 // 0..15
        int b = i >> 2;
        int t = ((i & 3) << 8) + tid;
        float acc[8];
#pragma unroll
        for (int h = 0; h < 8; h++) acc[h] = bp[h];
        const float* zp = z + (size_t)b * C_ * T_ + t;
#pragma unroll 4
        for (int c = 0; c < C_; c++) {
            float zv = zp[(size_t)c * T_];
            float4 wa = *(const float4*)&Wp[c * 8];
            float4 wb = *(const float4*)&Wp[c * 8 + 4];
            acc[0] += zv * wa.x; acc[1] += zv * wa.y;
            acc[2] += zv * wa.z; acc[3] += zv * wa.w;
            acc[4] += zv * wb.x; acc[5] += zv * wb.y;
            acc[6] += zv * wb.z; acc[7] += zv * wb.w;
        }
        int row = b * T_ + t;
        *(float4*)(g_Xp + row * 8)     = make_float4(acc[0], acc[1], acc[2], acc[3]);
        *(float4*)(g_Xp + row * 8 + 4) = make_float4(acc[4], acc[5], acc[6], acc[7]);
    }
}

// =====================  split-tf32 proj GEMM (R11 frozen config)  =====================
#define PAW 2560
#define PBW 2176
#define PROJ_SMEM ((3*(PAW+PBW))*4)   // 56832 B

__global__ __launch_bounds__(256, 2) void k_proj_mma(
    const float* __restrict__ cb,
    const float* __restrict__ Wq, const float* __restrict__ bq,
    const float* __restrict__ Wk, const float* __restrict__ bk,
    const float* __restrict__ Wv, const float* __restrict__ bv) {
    extern __shared__ __align__(16) unsigned char smraw[];
    const uint32_t smb = (uint32_t)__cvta_generic_to_shared(smraw);

    const float *A, *Bm, *bias; float* C;
    int zid = blockIdx.z;
    if (zid == 0)      { A = g_hs; Bm = Wq; bias = bq; C = g_Xq; }
    else if (zid == 1) { A = cb;   Bm = Wk; bias = bk; C = g_kh; }
    else               { A = cb;   Bm = Wv; bias = bv; C = g_value; }

    const int tid = threadIdx.x;
    const int wid = tid >> 5, lane = tid & 31;
    const int warpM = wid >> 1, warpN = wid & 1;
    const int m0 = blockIdx.y << 7, n0 = blockIdx.x << 7;
    const int ar = tid >> 2, ac = (tid & 3) << 2;
    const int br = tid >> 4, bc = (tid & 15) << 3;
    const int gid = lane >> 2, tig = lane & 3;

    const float* Ag = A + (size_t)(m0 + ar) * C_ + ac;

    const uint32_t dA0 = (uint32_t)(ar * 20 + ac) * 4;
    const uint32_t dA1 = (uint32_t)((ar + 64) * 20 + ac) * 4;
    const uint32_t dB0 = (uint32_t)(br * 136 + bc) * 4;
    const uint32_t dB1 = dB0 + 16;

#define PROJ_ISSUE(s) do { \
    const int _b = (s) % 3; \
    const uint32_t _ab = smb + (uint32_t)_b * (PAW * 4); \
    const uint32_t _bb = smb + (uint32_t)(3 * PAW + _b * PBW) * 4; \
    const float* _A = Ag + (s) * 16; \
    const float* _B = Bm + (size_t)((s) * 16 + br) * 512 + n0 + bc; \
    cp16(_ab + dA0, _A); \
    cp16(_ab + dA1, _A + 64 * C_); \
    cp16(_bb + dB0, _B); \
    cp16(_bb + dB1, _B + 4); \
    CP_COMMIT(); \
} while (0)

    PROJ_ISSUE(0);
    PROJ_ISSUE(1);

    float acc[2][8][4] = {};
    for (int t = 0; t < 32; ++t) {
        const int buf = t % 3;
        if (t + 1 < 32) CP_WAIT1(); else CP_WAIT0();
        __syncthreads();
        if (t + 2 < 32) PROJ_ISSUE(t + 2);

        const float* ASf = (const float*)smraw + buf * PAW;
        const float* BSf = (const float*)smraw + 3 * PAW + buf * PBW;
#pragma unroll
        for (int ks8 = 0; ks8 < 2; ks8++) {
            const int kb = ks8 * 8 + tig;
            uint32_t ah[2][4], al[2][4];
#pragma unroll
            for (int mt = 0; mt < 2; mt++) {
                int r = warpM * 32 + mt * 16 + gid;
                float x0 = ASf[r * 20 + kb];
                float x1 = ASf[(r + 8) * 20 + kb];
                float x2 = ASf[r * 20 + kb + 4];
                float x3 = ASf[(r + 8) * 20 + kb + 4];
                split1(x0, ah[mt][0], al[mt][0]);
                split1(x1, ah[mt][1], al[mt][1]);
                split1(x2, ah[mt][2], al[mt][2]);
                split1(x3, ah[mt][3], al[mt][3]);
            }
#pragma unroll
            for (int ntp = 0; ntp < 4; ntp++) {
                const int nt0 = ntp * 2, nt1 = nt0 + 1;
                const int c0 = warpN * 64 + ntp * 16 + gid;
                const int c1 = c0 + 8;
                float y00 = BSf[kb * 136 + c0];
                float y01 = BSf[(kb + 4) * 136 + c0];
                float y10 = BSf[kb * 136 + c1];
                float y11 = BSf[(kb + 4) * 136 + c1];
                uint32_t bh00, bl00, bh01, bl01, bh10, bl10, bh11, bl11;
                split1(y00, bh00, bl00);
                split1(y01, bh01, bl01);
                split1(y10, bh10, bl10);
                split1(y11, bh11, bl11);
                // per-acc term order (hh, hl, lh) preserved -> bit-identical sums
                MMA_TF32(acc[0][nt0], ah[0], bh00, bh01);
                MMA_TF32(acc[1][nt0], ah[1], bh00, bh01);
                MMA_TF32(acc[0][nt1], ah[0], bh10, bh11);
                MMA_TF32(acc[1][nt1], ah[1], bh10, bh11);
                MMA_TF32(acc[0][nt0], ah[0], bl00, bl01);
                MMA_TF32(acc[1][nt0], ah[1], bl00, bl01);
                MMA_TF32(acc[0][nt1], ah[0], bl10, bl11);
                MMA_TF32(acc[1][nt1], ah[1], bl10, bl11);
                MMA_TF32(acc[0][nt0], al[0], bh00, bh01);
                MMA_TF32(acc[1][nt0], al[1], bh00, bh01);
                MMA_TF32(acc[0][nt1], al[0], bh10, bh11);
                MMA_TF32(acc[1][nt1], al[1], bh10, bh11);
            }
        }
        __syncthreads();
    }

#pragma unroll
    for (int mt = 0; mt < 2; mt++) {
#pragma unroll
        for (int nt = 0; nt < 8; nt++) {
            int row = m0 + warpM * 32 + mt * 16 + gid;
            int col = n0 + warpN * 64 + nt * 8 + 2 * tig;
            float b0 = bias[col], b1 = bias[col + 1];
            float2 v0 = make_float2(acc[mt][nt][0] + b0, acc[mt][nt][1] + b1);
            float2 v1 = make_float2(acc[mt][nt][2] + b0, acc[mt][nt][3] + b1);
            *(float2*)(C + (size_t)row * C_ + col)       = v0;
            *(float2*)(C + (size_t)(row + 8) * C_ + col) = v1;
        }
    }
#undef PROJ_ISSUE
}

// =====================  fused rmsnorm + combine  =====================
__device__ __forceinline__ float head_rms_scale(float x, int d, float* ws) {
    float s = x * x;
#pragma unroll
    for (int o = 16; o; o >>= 1) s += __shfl_xor_sync(0xffffffffu, s, o);
    if ((d & 31) == 0) ws[d >> 5] = s;
    __syncthreads();
    int h = d >> 6;
    float tot = ws[2*h] + ws[2*h + 1];
    return rsqrtf(tot * (1.0f/64.0f) + 1e-5f);
}

__device__ __forceinline__ float block_sum_sq(float v, int d, float* s2) {
    float s = v * v;
#pragma unroll
    for (int o = 16; o; o >>= 1) s += __shfl_xor_sync(0xffffffffu, s, o);
    if ((d & 31) == 0) s2[d >> 5] = s;
    __syncthreads();
    float tot = 0.0f;
    if (d == 0) {
#pragma unroll
        for (int i = 0; i < 16; i++) tot += s2[i];
    }
    return tot;
}

__global__ void k_norms(const float* __restrict__ gq, const float* __restrict__ gk) {
    __shared__ float ws[16];
    __shared__ float s2[16];
    const int b = blockIdx.x;
    const int d = threadIdx.x;
    const int h = d >> 6;

    if (b < V_) {
        int row = b;
        float x = g_kh[(size_t)row*C_ + d];
        float r = head_rms_scale(x, d, ws);
        float v = x * r * gk[d & 63];
        g_kh[(size_t)row*C_ + d] = v;
        g_Kh[(size_t)row*C_ + d] = __float2bfloat16(v);
        __syncthreads();
        float n2 = block_sum_sq(v, d, s2);
        if (d == 0) atomicMax(&g_knmax_i, __float_as_int(sqrtf(n2)));
    } else if (b < V_ + MFULL) {
        int row = b - V_;
        float x = g_Xq[(size_t)row*C_ + d];
        float r = head_rms_scale(x, d, ws);
        float c = g_Xp[row*H_ + h];
        float v = x * r * gq[d & 63] * c * COMB_SCALE;
        g_Q[(size_t)row*C_ + d] = v;
        g_Qh[(size_t)row*C_ + d] = __float2bfloat16(v);
        __syncthreads();
        float n2 = block_sum_sq(v, d, s2);
        if (d == 0) g_qnorm[row] = sqrtf(n2);
    } else {
        int row = b - V_ - MFULL;
        int fr = (row >> 8) * T_ + (row & 255) * 4;
        const float* p = g_Xq + (size_t)fr*C_ + d;
        float x = 0.25f * (p[0] + p[C_] + p[2*C_] + p[3*C_]);
        float r = head_rms_scale(x, d, ws);
        const float* pc = g_Xp + fr*H_ + h;
        float c = 0.25f * (pc[0] + pc[H_] + pc[2*H_] + pc[3*H_]);
        float v = x * r * gq[d & 63] * c * COMB_SCALE;
        g_Q[(size_t)(MFULL + row)*C_ + d] = v;
        g_Qh[(size_t)(MFULL + row)*C_ + d] = __float2bfloat16(v);
        __syncthreads();
        float n2 = block_sum_sq(v, d, s2);
        if (d == 0) g_qnorm[MFULL + row] = sqrtf(n2);
    }
}

// =====================  bf16 logits GEMM, cp.async 3-stage  =====================
#define LAW 2560
#define LOG_SMEM ((6 * LAW) * 4)

__global__ __launch_bounds__(256, 2) void k_logits_mma() {
    extern __shared__ __align__(16) unsigned char smraw[];
    const uint32_t smb = (uint32_t)__cvta_generic_to_shared(smraw);
    const int tid = threadIdx.x;
    const int wid = tid >> 5, lane = tid & 31;
    const int warpM = wid >> 1, warpN = wid & 1;
    const int m0 = blockIdx.y << 7, n0 = blockIdx.x << 7;
    const int gid = lane >> 2, tig = lane & 3;
    const int row = tid >> 1, hf = tid & 1;

    const char* Ag = (const char*)(g_Qh + (size_t)(m0 + row) * C_) + hf * 32;
    const char* Bg = (const char*)(g_Kh + (size_t)(n0 + row) * C_) + hf * 32;
    const uint32_t dT = (uint32_t)(row * 20 + hf * 8) * 4;

#define LOG_ISSUE(s) do { \
    const int _b = (s) % 3; \
    const uint32_t _a = smb + (uint32_t)(_b * LAW) * 4 + dT; \
    const uint32_t _bb = smb + (uint32_t)((3 + _b) * LAW) * 4 + dT; \
    cp16(_a,       Ag + (s) * 64); \
    cp16(_a + 16,  Ag + (s) * 64 + 16); \
    cp16(_bb,      Bg + (s) * 64); \
    cp16(_bb + 16, Bg + (s) * 64 + 16); \
    CP_COMMIT(); \
} while (0)

    LOG_ISSUE(0);
    LOG_ISSUE(1);

    float acc[2][8][4] = {};
    for (int t = 0; t < 16; ++t) {
        const int buf = t % 3;
        if (t + 1 < 16) CP_WAIT1(); else CP_WAIT0();
        __syncthreads();
        if (t + 2 < 16) LOG_ISSUE(t + 2);

        const uint32_t* As = (const uint32_t*)smraw + buf * LAW;
        const uint32_t* Bs = (const uint32_t*)smraw + (3 + buf) * LAW;
#pragma unroll
        for (int ku = 0; ku < 16; ku += 8) {
            uint32_t af[2][4];
#pragma unroll
            for (int mt = 0; mt < 2; mt++) {
                int r = warpM * 32 + mt * 16 + gid;
                af[mt][0] = As[r * 20 + ku + tig];
                af[mt][1] = As[(r + 8) * 20 + ku + tig];
                af[mt][2] = As[r * 20 + ku + tig + 4];
                af[mt][3] = As[(r + 8) * 20 + ku + tig + 4];
            }
#pragma unroll
            for (int nt = 0; nt < 8; nt++) {
                int c = warpN * 64 + nt * 8 + gid;
                uint32_t b0 = Bs[c * 20 + ku + tig];
                uint32_t b1 = Bs[c * 20 + ku + tig + 4];
                MMA_BF16(acc[0][nt], af[0], b0, b1);
                MMA_BF16(acc[1][nt], af[1], b0, b1);
            }
        }
        __syncthreads();
    }

#pragma unroll
    for (int mt = 0; mt < 2; mt++) {
#pragma unroll
        for (int nt = 0; nt < 8; nt++) {
            int r = m0 + warpM * 32 + mt * 16 + gid;
            int col = n0 + warpN * 64 + nt * 8 + 2 * tig;
            __nv_bfloat162 p0 = __floats2bfloat162_rn(acc[mt][nt][0], acc[mt][nt][1]);
            __nv_bfloat162 p1 = __floats2bfloat162_rn(acc[mt][nt][2], acc[mt][nt][3]);
            *(__nv_bfloat162*)(g_logitsh + (size_t)r * V_ + col)       = p0;
            *(__nv_bfloat162*)(g_logitsh + (size_t)(r + 8) * V_ + col) = p1;
        }
    }
#undef LOG_ISSUE
}

// =====================  margin select + warp-parallel exact rescore (+hist)  =====================
__global__ __launch_bounds__(256, 4) void k_select() {
    __shared__ float s_red[8];
    __shared__ float s_max;
    __shared__ int   s_cnt;
    __shared__ int   s_cand[128];
    __shared__ float s_cval[128];
    __shared__ float sq[C_];
    const int row = blockIdx.x;
    const int tid = threadIdx.x;
    const int wid = tid >> 5, lane = tid & 31;
    const uint4* L = (const uint4*)(g_logitsh + (size_t)row * V_);

    *(float2*)&sq[tid*2] = *(const float2*)(g_Q + (size_t)row * C_ + tid*2);

    uint4 u0 = L[tid], u1 = L[tid + 256];
    float vals[16];
    {
        uint32_t w[8] = {u0.x,u0.y,u0.z,u0.w, u1.x,u1.y,u1.z,u1.w};
#pragma unroll
        for (int q = 0; q < 8; q++) {
            float2 f = __bfloat1622float2(*(__nv_bfloat162*)&w[q]);
            vals[q*2] = f.x; vals[q*2+1] = f.y;
        }
    }
    float vmax = -1e30f;
#pragma unroll
    for (int q = 0; q < 16; q++) vmax = fmaxf(vmax, vals[q]);
#pragma unroll
    for (int o = 16; o; o >>= 1) vmax = fmaxf(vmax, __shfl_xor_sync(0xffffffffu, vmax, o));
    if (lane == 0) s_red[wid] = vmax;
    if (tid == 0) s_cnt = 0;
    __syncthreads();
    if (tid == 0) {
        float m = s_red[0];
#pragma unroll
        for (int i = 1; i < 8; i++) m = fmaxf(m, s_red[i]);
        s_max = m;
    }
    __syncthreads();
    const float kn = __int_as_float(g_knmax_i);
    const float margin = 0.022f * g_qnorm[row] * kn + 1e-6f;
    const float thr = s_max - margin;

#pragma unroll
    for (int q = 0; q < 16; q++) {
        if (vals[q] >= thr) {
            int base = (q < 8) ? (tid * 8 + q) : (2048 + tid * 8 + (q - 8));
            int p = atomicAdd(&s_cnt, 1);
            if (p < 128) s_cand[p] = base;
        }
    }
    __syncthreads();
    int cnt = min(s_cnt, 128);

    for (int c = wid; c < cnt; c += 8) {
        int n = s_cand[c];
        const float* kr = g_kh + (size_t)n * C_;
        float p = 0.0f;
#pragma unroll
        for (int i = 0; i < 16; i++) p += sq[i*32 + lane] * kr[i*32 + lane];
#pragma unroll
        for (int o = 16; o; o >>= 1) p += __shfl_xor_sync(0xffffffffu, p, o);
        if (lane == 0) s_cval[c] = p;
    }
    __syncthreads();
    if (tid == 0) {
        float best_v = -1e30f;
        int best_n = 1 << 30;
        for (int c = 0; c < cnt; c++) {
            float v = s_cval[c];
            int n = s_cand[c];
            if (v > best_v || (v == best_v && n < best_n)) { best_v = v; best_n = n; }
        }
        g_idx[row] = best_n;
        if (row < MFULL) atomicAdd(&g_cnt[best_n], 1);
    }
}

// =====================  output: z_hat gather+interp; last block does perplexity  =====================
__global__ void k_out(float* __restrict__ out) {
    if (blockIdx.x == 8192) {
        __shared__ float sm_[256];
        int tid = threadIdx.x;
        float s = 0.0f;
        for (int j = tid; j < V_; j += 256) {
            float p = (float)g_cnt[j] * (1.0f / 4096.0f);
            s += p * logf(p + 1e-7f);
        }
        sm_[tid] = s;
        __syncthreads();
        for (int o = 128; o; o >>= 1) {
            if (tid < o) sm_[tid] += sm_[tid + o];
            __syncthreads();
        }
        if (tid == 0) out[ZHAT_ELEMS] = expf(-sm_[0]);
        return;
    }
    int idx = blockIdx.x * blockDim.x + threadIdx.x;
    int t = idx & (T_ - 1);
    int d = (idx >> 10) & 511;
    int b = idx >> 19;
    float pos = (t + 0.5f) * ((float)Q_ / (float)T_) - 0.5f;
    pos = fminf(fmaxf(pos, 0.0f), (float)(Q_ - 1));
    int i0 = (int)pos;
    int i1 = min(i0 + 1, Q_ - 1);
    float w = pos - (float)i0;
    int n0 = g_idx[MFULL + b*Q_ + i0];
    int n1 = g_idx[MFULL + b*Q_ + i1];
    out[idx] = (1.0f - w) * g_value[(size_t)n0*C_ + d] + w * g_value[(size_t)n1*C_ + d];
}

// ---------------------------------------------------------------------------
extern "C" void kernel_launch(void* const* d_in, const int* in_sizes, int n_in,
                              void* d_out, int out_size) {
    const float* z        = (const float*)d_in[0];
    const float* codebook = (const float*)d_in[2];
    const float* Wq = (const float*)d_in[3];
    const float* bq = (const float*)d_in[4];
    const float* Wk = (const float*)d_in[5];
    const float* bk = (const float*)d_in[6];
    const float* Wv = (const float*)d_in[7];
    const float* bv = (const float*)d_in[8];
    const float* Wp = (const float*)d_in[9];
    const float* bp = (const float*)d_in[10];
    const float* gq = (const float*)d_in[11];
    const float* gk = (const float*)d_in[12];
    float* out = (float*)d_out;

    cudaFuncSetAttribute(k_proj_mma, cudaFuncAttributeMaxDynamicSharedMemorySize, PROJ_SMEM);
    cudaFuncSetAttribute(k_logits_mma, cudaFuncAttributeMaxDynamicSharedMemorySize, LOG_SMEM);

    k_pre<<<2064, 256>>>(z, Wp, bp);                                          // 1 (init+transpose+xp)
    k_proj_mma<<<dim3(4, 32, 3), 256, PROJ_SMEM>>>(codebook, Wq, bq, Wk, bk, Wv, bv); // 2
    k_norms<<<V_ + MFULL + MREST, 512>>>(gq, gk);                             // 3
    k_logits_mma<<<dim3(V_/128, MTOT/128), 256, LOG_SMEM>>>();                // 4 (profiled)
    k_select<<<MTOT, 256>>>();                                                // 5
    k_out<<<8193, 256>>>(out);                                                // 6
}

// round 16
// speedup vs baseline: 1.2146x; 1.2146x over previous
#include <cuda_runtime.h>
#include <cuda_bf16.h>
#include <cstdint>

// Problem constants
#define B_    4
#define T_    1024
#define C_    512
#define V_    4096
#define H_    8
#define Q_    256
#define MFULL 4096
#define MREST 1024
#define MTOT  5120
#define ZHAT_ELEMS (B_*C_*T_)
#define COMB_SCALE 0.044194173824159216f

// ---- scratch ----
__device__ float g_hs[MFULL*C_];
__device__ float g_Xq[MFULL*C_];
__device__ float g_Xp[MFULL*H_];
__device__ float g_value[V_*C_];
__device__ float g_kh[V_*C_];
__device__ float g_Q[MTOT*C_];
__device__ __nv_bfloat16 g_Qh[MTOT*C_];
__device__ __nv_bfloat16 g_Kh[V_*C_];
__device__ __nv_bfloat16 g_logitsh[(size_t)MTOT*V_];
__device__ float g_qnorm[MTOT];
__device__ int   g_knmax_i;
__device__ int   g_idx[MTOT];
__device__ int   g_cnt[V_];

// =====================  mma / cp.async helpers  =====================
#define MMA_TF32(c, a, b0, b1) \
    asm volatile("mma.sync.aligned.m16n8k8.row.col.f32.tf32.tf32.f32 " \
        "{%0,%1,%2,%3}, {%4,%5,%6,%7}, {%8,%9}, {%0,%1,%2,%3};" \
        : "+f"((c)[0]), "+f"((c)[1]), "+f"((c)[2]), "+f"((c)[3]) \
        : "r"((a)[0]), "r"((a)[1]), "r"((a)[2]), "r"((a)[3]), "r"(b0), "r"(b1))

#define MMA_BF16(c, a, b0, b1) \
    asm volatile("mma.sync.aligned.m16n8k16.row.col.f32.bf16.bf16.f32 " \
        "{%0,%1,%2,%3}, {%4,%5,%6,%7}, {%8,%9}, {%0,%1,%2,%3};" \
        : "+f"((c)[0]), "+f"((c)[1]), "+f"((c)[2]), "+f"((c)[3]) \
        : "r"((a)[0]), "r"((a)[1]), "r"((a)[2]), "r"((a)[3]), "r"(b0), "r"(b1))

__device__ __forceinline__ void cp16(uint32_t dst, const void* src) {
    asm volatile("cp.async.cg.shared.global [%0], [%1], 16;" :: "r"(dst), "l"(src));
}
#define CP_COMMIT() asm volatile("cp.async.commit_group;" ::: "memory")
#define CP_WAIT2()  asm volatile("cp.async.wait_group 2;" ::: "memory")
#define CP_WAIT1()  asm volatile("cp.async.wait_group 1;" ::: "memory")
#define CP_WAIT0()  asm volatile("cp.async.wait_group 0;" ::: "memory")

__device__ __forceinline__ uint32_t tf32_of(float x) {
    uint32_t r; asm("cvt.rna.tf32.f32 %0, %1;" : "=r"(r) : "f"(x)); return r;
}
__device__ __forceinline__ void split1(float x, uint32_t& h, uint32_t& l) {
    h = tf32_of(x);
    l = tf32_of(x - __uint_as_float(h));
}

// =====================  small kernels  =====================
// transpose z (B,C,T) -> hs; block 0 also inits
__global__ void k_transpose(const float* __restrict__ z) {
    __shared__ float tile[32][33];
    int b = blockIdx.z, c0 = blockIdx.x << 5, t0 = blockIdx.y << 5;
    int tx = threadIdx.x, ty = threadIdx.y;
    if (blockIdx.x == 0 && blockIdx.y == 0 && blockIdx.z == 0) {
        int tid = ty * 32 + tx;
        for (int i = tid; i < V_; i += 256) g_cnt[i] = 0;
        if (tid == 0) g_knmax_i = 0;
    }
#pragma unroll
    for (int j = 0; j < 4; j++)
        tile[ty + 8*j][tx] = z[(b*C_ + c0 + ty + 8*j)*T_ + t0 + tx];
    __syncthreads();
#pragma unroll
    for (int j = 0; j < 4; j++)
        g_hs[(b*T_ + t0 + ty + 8*j)*C_ + c0 + tx] = tile[tx][ty + 8*j];
}

__global__ __launch_bounds__(256) void k_xp(const float* __restrict__ Wp,
                                            const float* __restrict__ bp) {
    __shared__ float w[C_ * H_];
    int tid = threadIdx.x;
    for (int i = tid * 4; i < C_ * H_; i += 1024)
        *(float4*)&w[i] = *(const float4*)&Wp[i];
    __syncthreads();
    int row = blockIdx.x * 256 + tid;
    const float* hsr = g_hs + (size_t)row * C_;
    float acc[8];
#pragma unroll
    for (int j = 0; j < 8; j++) acc[j] = bp[j];
#pragma unroll 4
    for (int k = 0; k < C_; k += 4) {
        float4 hv = *(const float4*)(hsr + k);
        float h[4] = {hv.x, hv.y, hv.z, hv.w};
#pragma unroll
        for (int i = 0; i < 4; i++) {
            float4 wa = *(const float4*)&w[(k + i) * 8];
            float4 wb = *(const float4*)&w[(k + i) * 8 + 4];
            acc[0] += h[i] * wa.x; acc[1] += h[i] * wa.y;
            acc[2] += h[i] * wa.z; acc[3] += h[i] * wa.w;
            acc[4] += h[i] * wb.x; acc[5] += h[i] * wb.y;
            acc[6] += h[i] * wb.z; acc[7] += h[i] * wb.w;
        }
    }
    *(float4*)(g_Xp + row * 8)     = make_float4(acc[0], acc[1], acc[2], acc[3]);
    *(float4*)(g_Xp + row * 8 + 4) = make_float4(acc[4], acc[5], acc[6], acc[7]);
}

// =====================  split-tf32 proj GEMM (R11 frozen config)  =====================
#define PAW 2560
#define PBW 2176
#define PROJ_SMEM ((3*(PAW+PBW))*4)   // 56832 B

__global__ __launch_bounds__(256, 2) void k_proj_mma(
    const float* __restrict__ cb,
    const float* __restrict__ Wq, const float* __restrict__ bq,
    const float* __restrict__ Wk, const float* __restrict__ bk,
    const float* __restrict__ Wv, const float* __restrict__ bv) {
    extern __shared__ __align__(16) unsigned char smraw[];
    const uint32_t smb = (uint32_t)__cvta_generic_to_shared(smraw);

    const float *A, *Bm, *bias; float* C;
    int zid = blockIdx.z;
    if (zid == 0)      { A = g_hs; Bm = Wq; bias = bq; C = g_Xq; }
    else if (zid == 1) { A = cb;   Bm = Wk; bias = bk; C = g_kh; }
    else               { A = cb;   Bm = Wv; bias = bv; C = g_value; }

    const int tid = threadIdx.x;
    const int wid = tid >> 5, lane = tid & 31;
    const int warpM = wid >> 1, warpN = wid & 1;
    const int m0 = blockIdx.y << 7, n0 = blockIdx.x << 7;
    const int ar = tid >> 2, ac = (tid & 3) << 2;
    const int br = tid >> 4, bc = (tid & 15) << 3;
    const int gid = lane >> 2, tig = lane & 3;

    const float* Ag = A + (size_t)(m0 + ar) * C_ + ac;

    const uint32_t dA0 = (uint32_t)(ar * 20 + ac) * 4;
    const uint32_t dA1 = (uint32_t)((ar + 64) * 20 + ac) * 4;
    const uint32_t dB0 = (uint32_t)(br * 136 + bc) * 4;
    const uint32_t dB1 = dB0 + 16;

#define PROJ_ISSUE(s) do { \
    const int _b = (s) % 3; \
    const uint32_t _ab = smb + (uint32_t)_b * (PAW * 4); \
    const uint32_t _bb = smb + (uint32_t)(3 * PAW + _b * PBW) * 4; \
    const float* _A = Ag + (s) * 16; \
    const float* _B = Bm + (size_t)((s) * 16 + br) * 512 + n0 + bc; \
    cp16(_ab + dA0, _A); \
    cp16(_ab + dA1, _A + 64 * C_); \
    cp16(_bb + dB0, _B); \
    cp16(_bb + dB1, _B + 4); \
    CP_COMMIT(); \
} while (0)

    PROJ_ISSUE(0);
    PROJ_ISSUE(1);

    float acc[2][8][4] = {};
    for (int t = 0; t < 32; ++t) {
        const int buf = t % 3;
        if (t + 1 < 32) CP_WAIT1(); else CP_WAIT0();
        __syncthreads();
        if (t + 2 < 32) PROJ_ISSUE(t + 2);

        const float* ASf = (const float*)smraw + buf * PAW;
        const float* BSf = (const float*)smraw + 3 * PAW + buf * PBW;
#pragma unroll
        for (int ks8 = 0; ks8 < 2; ks8++) {
            const int kb = ks8 * 8 + tig;
            uint32_t ah[2][4], al[2][4];
#pragma unroll
            for (int mt = 0; mt < 2; mt++) {
                int r = warpM * 32 + mt * 16 + gid;
                float x0 = ASf[r * 20 + kb];
                float x1 = ASf[(r + 8) * 20 + kb];
                float x2 = ASf[r * 20 + kb + 4];
                float x3 = ASf[(r + 8) * 20 + kb + 4];
                split1(x0, ah[mt][0], al[mt][0]);
                split1(x1, ah[mt][1], al[mt][1]);
                split1(x2, ah[mt][2], al[mt][2]);
                split1(x3, ah[mt][3], al[mt][3]);
            }
#pragma unroll
            for (int ntp = 0; ntp < 4; ntp++) {
                const int nt0 = ntp * 2, nt1 = nt0 + 1;
                const int c0 = warpN * 64 + ntp * 16 + gid;
                const int c1 = c0 + 8;
                float y00 = BSf[kb * 136 + c0];
                float y01 = BSf[(kb + 4) * 136 + c0];
                float y10 = BSf[kb * 136 + c1];
                float y11 = BSf[(kb + 4) * 136 + c1];
                uint32_t bh00, bl00, bh01, bl01, bh10, bl10, bh11, bl11;
                split1(y00, bh00, bl00);
                split1(y01, bh01, bl01);
                split1(y10, bh10, bl10);
                split1(y11, bh11, bl11);
                // per-acc term order (hh, hl, lh) preserved -> bit-identical sums
                MMA_TF32(acc[0][nt0], ah[0], bh00, bh01);
                MMA_TF32(acc[1][nt0], ah[1], bh00, bh01);
                MMA_TF32(acc[0][nt1], ah[0], bh10, bh11);
                MMA_TF32(acc[1][nt1], ah[1], bh10, bh11);
                MMA_TF32(acc[0][nt0], ah[0], bl00, bl01);
                MMA_TF32(acc[1][nt0], ah[1], bl00, bl01);
                MMA_TF32(acc[0][nt1], ah[0], bl10, bl11);
                MMA_TF32(acc[1][nt1], ah[1], bl10, bl11);
                MMA_TF32(acc[0][nt0], al[0], bh00, bh01);
                MMA_TF32(acc[1][nt0], al[1], bh00, bh01);
                MMA_TF32(acc[0][nt1], al[0], bh10, bh11);
                MMA_TF32(acc[1][nt1], al[1], bh10, bh11);
            }
        }
        __syncthreads();
    }

#pragma unroll
    for (int mt = 0; mt < 2; mt++) {
#pragma unroll
        for (int nt = 0; nt < 8; nt++) {
            int row = m0 + warpM * 32 + mt * 16 + gid;
            int col = n0 + warpN * 64 + nt * 8 + 2 * tig;
            float b0 = bias[col], b1 = bias[col + 1];
            float2 v0 = make_float2(acc[mt][nt][0] + b0, acc[mt][nt][1] + b1);
            float2 v1 = make_float2(acc[mt][nt][2] + b0, acc[mt][nt][3] + b1);
            *(float2*)(C + (size_t)row * C_ + col)       = v0;
            *(float2*)(C + (size_t)(row + 8) * C_ + col) = v1;
        }
    }
#undef PROJ_ISSUE
}

// =====================  fused rmsnorm + combine  =====================
__device__ __forceinline__ float head_rms_scale(float x, int d, float* ws) {
    float s = x * x;
#pragma unroll
    for (int o = 16; o; o >>= 1) s += __shfl_xor_sync(0xffffffffu, s, o);
    if ((d & 31) == 0) ws[d >> 5] = s;
    __syncthreads();
    int h = d >> 6;
    float tot = ws[2*h] + ws[2*h + 1];
    return rsqrtf(tot * (1.0f/64.0f) + 1e-5f);
}

__device__ __forceinline__ float block_sum_sq(float v, int d, float* s2) {
    float s = v * v;
#pragma unroll
    for (int o = 16; o; o >>= 1) s += __shfl_xor_sync(0xffffffffu, s, o);
    if ((d & 31) == 0) s2[d >> 5] = s;
    __syncthreads();
    float tot = 0.0f;
    if (d == 0) {
#pragma unroll
        for (int i = 0; i < 16; i++) tot += s2[i];
    }
    return tot;
}

__global__ void k_norms(const float* __restrict__ gq, const float* __restrict__ gk) {
    __shared__ float ws[16];
    __shared__ float s2[16];
    const int b = blockIdx.x;
    const int d = threadIdx.x;
    const int h = d >> 6;

    if (b < V_) {
        int row = b;
        float x = g_kh[(size_t)row*C_ + d];
        float r = head_rms_scale(x, d, ws);
        float v = x * r * gk[d & 63];
        g_kh[(size_t)row*C_ + d] = v;
        g_Kh[(size_t)row*C_ + d] = __float2bfloat16(v);
        __syncthreads();
        float n2 = block_sum_sq(v, d, s2);
        if (d == 0) atomicMax(&g_knmax_i, __float_as_int(sqrtf(n2)));
    } else if (b < V_ + MFULL) {
        int row = b - V_;
        float x = g_Xq[(size_t)row*C_ + d];
        float r = head_rms_scale(x, d, ws);
        float c = g_Xp[row*H_ + h];
        float v = x * r * gq[d & 63] * c * COMB_SCALE;
        g_Q[(size_t)row*C_ + d] = v;
        g_Qh[(size_t)row*C_ + d] = __float2bfloat16(v);
        __syncthreads();
        float n2 = block_sum_sq(v, d, s2);
        if (d == 0) g_qnorm[row] = sqrtf(n2);
    } else {
        int row = b - V_ - MFULL;
        int fr = (row >> 8) * T_ + (row & 255) * 4;
        const float* p = g_Xq + (size_t)fr*C_ + d;
        float x = 0.25f * (p[0] + p[C_] + p[2*C_] + p[3*C_]);
        float r = head_rms_scale(x, d, ws);
        const float* pc = g_Xp + fr*H_ + h;
        float c = 0.25f * (pc[0] + pc[H_] + pc[2*H_] + pc[3*H_]);
        float v = x * r * gq[d & 63] * c * COMB_SCALE;
        g_Q[(size_t)(MFULL + row)*C_ + d] = v;
        g_Qh[(size_t)(MFULL + row)*C_ + d] = __float2bfloat16(v);
        __syncthreads();
        float n2 = block_sum_sq(v, d, s2);
        if (d == 0) g_qnorm[MFULL + row] = sqrtf(n2);
    }
}

// =====================  bf16 logits GEMM, cp.async 4-stage deep pipeline  =====================
#define LAW 2560
#define LOG_SMEM ((8 * LAW) * 4)   // 81920 B: 4 A-buffers + 4 B-buffers

__global__ __launch_bounds__(256, 2) void k_logits_mma() {
    extern __shared__ __align__(16) unsigned char smraw[];
    const uint32_t smb = (uint32_t)__cvta_generic_to_shared(smraw);
    const int tid = threadIdx.x;
    const int wid = tid >> 5, lane = tid & 31;
    const int warpM = wid >> 1, warpN = wid & 1;
    const int m0 = blockIdx.y << 7, n0 = blockIdx.x << 7;
    const int gid = lane >> 2, tig = lane & 3;
    const int row = tid >> 1, hf = tid & 1;

    const char* Ag = (const char*)(g_Qh + (size_t)(m0 + row) * C_) + hf * 32;
    const char* Bg = (const char*)(g_Kh + (size_t)(n0 + row) * C_) + hf * 32;
    const uint32_t dT = (uint32_t)(row * 20 + hf * 8) * 4;

#define LOG_ISSUE(s) do { \
    const int _b = (s) % 4; \
    const uint32_t _a = smb + (uint32_t)(_b * LAW) * 4 + dT; \
    const uint32_t _bb = smb + (uint32_t)((4 + _b) * LAW) * 4 + dT; \
    cp16(_a,       Ag + (s) * 64); \
    cp16(_a + 16,  Ag + (s) * 64 + 16); \
    cp16(_bb,      Bg + (s) * 64); \
    cp16(_bb + 16, Bg + (s) * 64 + 16); \
    CP_COMMIT(); \
} while (0)

    LOG_ISSUE(0);
    LOG_ISSUE(1);
    LOG_ISSUE(2);

    float acc[2][8][4] = {};
    for (int t = 0; t < 16; ++t) {
        const int buf = t % 4;
        if (t <= 13) CP_WAIT2(); else if (t == 14) CP_WAIT1(); else CP_WAIT0();
        __syncthreads();
        if (t + 3 < 16) LOG_ISSUE(t + 3);

        const uint32_t* As = (const uint32_t*)smraw + buf * LAW;
        const uint32_t* Bs = (const uint32_t*)smraw + (4 + buf) * LAW;
#pragma unroll
        for (int ku = 0; ku < 16; ku += 8) {
            uint32_t af[2][4];
#pragma unroll
            for (int mt = 0; mt < 2; mt++) {
                int r = warpM * 32 + mt * 16 + gid;
                af[mt][0] = As[r * 20 + ku + tig];
                af[mt][1] = As[(r + 8) * 20 + ku + tig];
                af[mt][2] = As[r * 20 + ku + tig + 4];
                af[mt][3] = As[(r + 8) * 20 + ku + tig + 4];
            }
#pragma unroll
            for (int nt = 0; nt < 8; nt++) {
                int c = warpN * 64 + nt * 8 + gid;
                uint32_t b0 = Bs[c * 20 + ku + tig];
                uint32_t b1 = Bs[c * 20 + ku + tig + 4];
                MMA_BF16(acc[0][nt], af[0], b0, b1);
                MMA_BF16(acc[1][nt], af[1], b0, b1);
            }
        }
        __syncthreads();
    }

#pragma unroll
    for (int mt = 0; mt < 2; mt++) {
#pragma unroll
        for (int nt = 0; nt < 8; nt++) {
            int r = m0 + warpM * 32 + mt * 16 + gid;
            int col = n0 + warpN * 64 + nt * 8 + 2 * tig;
            __nv_bfloat162 p0 = __floats2bfloat162_rn(acc[mt][nt][0], acc[mt][nt][1]);
            __nv_bfloat162 p1 = __floats2bfloat162_rn(acc[mt][nt][2], acc[mt][nt][3]);
            *(__nv_bfloat162*)(g_logitsh + (size_t)r * V_ + col)       = p0;
            *(__nv_bfloat162*)(g_logitsh + (size_t)(r + 8) * V_ + col) = p1;
        }
    }
#undef LOG_ISSUE
}

// =====================  margin select + warp-parallel exact rescore (+hist)  =====================
__global__ __launch_bounds__(256, 4) void k_select() {
    __shared__ float s_red[8];
    __shared__ float s_max;
    __shared__ int   s_cnt;
    __shared__ int   s_cand[128];
    __shared__ float s_cval[128];
    __shared__ float sq[C_];
    const int row = blockIdx.x;
    const int tid = threadIdx.x;
    const int wid = tid >> 5, lane = tid & 31;
    const uint4* L = (const uint4*)(g_logitsh + (size_t)row * V_);

    *(float2*)&sq[tid*2] = *(const float2*)(g_Q + (size_t)row * C_ + tid*2);

    uint4 u0 = L[tid], u1 = L[tid + 256];
    float vals[16];
    {
        uint32_t w[8] = {u0.x,u0.y,u0.z,u0.w, u1.x,u1.y,u1.z,u1.w};
#pragma unroll
        for (int q = 0; q < 8; q++) {
            float2 f = __bfloat1622float2(*(__nv_bfloat162*)&w[q]);
            vals[q*2] = f.x; vals[q*2+1] = f.y;
        }
    }
    float vmax = -1e30f;
#pragma unroll
    for (int q = 0; q < 16; q++) vmax = fmaxf(vmax, vals[q]);
#pragma unroll
    for (int o = 16; o; o >>= 1) vmax = fmaxf(vmax, __shfl_xor_sync(0xffffffffu, vmax, o));
    if (lane == 0) s_red[wid] = vmax;
    if (tid == 0) s_cnt = 0;
    __syncthreads();
    if (tid == 0) {
        float m = s_red[0];
#pragma unroll
        for (int i = 1; i < 8; i++) m = fmaxf(m, s_red[i]);
        s_max = m;
    }
    __syncthreads();
    const float kn = __int_as_float(g_knmax_i);
    const float margin = 0.022f * g_qnorm[row] * kn + 1e-6f;
    const float thr = s_max - margin;

#pragma unroll
    for (int q = 0; q < 16; q++) {
        if (vals[q] >= thr) {
            int base = (q < 8) ? (tid * 8 + q) : (2048 + tid * 8 + (q - 8));
            int p = atomicAdd(&s_cnt, 1);
            if (p < 128) s_cand[p] = base;
        }
    }
    __syncthreads();
    int cnt = min(s_cnt, 128);

    for (int c = wid; c < cnt; c += 8) {
        int n = s_cand[c];
        const float* kr = g_kh + (size_t)n * C_;
        float p = 0.0f;
#pragma unroll
        for (int i = 0; i < 16; i++) p += sq[i*32 + lane] * kr[i*32 + lane];
#pragma unroll
        for (int o = 16; o; o >>= 1) p += __shfl_xor_sync(0xffffffffu, p, o);
        if (lane == 0) s_cval[c] = p;
    }
    __syncthreads();
    if (tid == 0) {
        float best_v = -1e30f;
        int best_n = 1 << 30;
        for (int c = 0; c < cnt; c++) {
            float v = s_cval[c];
            int n = s_cand[c];
            if (v > best_v || (v == best_v && n < best_n)) { best_v = v; best_n = n; }
        }
        g_idx[row] = best_n;
        if (row < MFULL) atomicAdd(&g_cnt[best_n], 1);
    }
}

// =====================  output: z_hat gather+interp; last block does perplexity  =====================
__global__ void k_out(float* __restrict__ out) {
    if (blockIdx.x == 8192) {
        __shared__ float sm_[256];
        int tid = threadIdx.x;
        float s = 0.0f;
        for (int j = tid; j < V_; j += 256) {
            float p = (float)g_cnt[j] * (1.0f / 4096.0f);
            s += p * logf(p + 1e-7f);
        }
        sm_[tid] = s;
        __syncthreads();
        for (int o = 128; o; o >>= 1) {
            if (tid < o) sm_[tid] += sm_[tid + o];
            __syncthreads();
        }
        if (tid == 0) out[ZHAT_ELEMS] = expf(-sm_[0]);
        return;
    }
    int idx = blockIdx.x * blockDim.x + threadIdx.x;
    int t = idx & (T_ - 1);
    int d = (idx >> 10) & 511;
    int b = idx >> 19;
    float pos = (t + 0.5f) * ((float)Q_ / (float)T_) - 0.5f;
    pos = fminf(fmaxf(pos, 0.0f), (float)(Q_ - 1));
    int i0 = (int)pos;
    int i1 = min(i0 + 1, Q_ - 1);
    float w = pos - (float)i0;
    int n0 = g_idx[MFULL + b*Q_ + i0];
    int n1 = g_idx[MFULL + b*Q_ + i1];
    out[idx] = (1.0f - w) * g_value[(size_t)n0*C_ + d] + w * g_value[(size_t)n1*C_ + d];
}

// ---------------------------------------------------------------------------
extern "C" void kernel_launch(void* const* d_in, const int* in_sizes, int n_in,
                              void* d_out, int out_size) {
    const float* z        = (const float*)d_in[0];
    const float* codebook = (const float*)d_in[2];
    const float* Wq = (const float*)d_in[3];
    const float* bq = (const float*)d_in[4];
    const float* Wk = (const float*)d_in[5];
    const float* bk = (const float*)d_in[6];
    const float* Wv = (const float*)d_in[7];
    const float* bv = (const float*)d_in[8];
    const float* Wp = (const float*)d_in[9];
    const float* bp = (const float*)d_in[10];
    const float* gq = (const float*)d_in[11];
    const float* gk = (const float*)d_in[12];
    float* out = (float*)d_out;

    cudaFuncSetAttribute(k_proj_mma, cudaFuncAttributeMaxDynamicSharedMemorySize, PROJ_SMEM);
    cudaFuncSetAttribute(k_logits_mma, cudaFuncAttributeMaxDynamicSharedMemorySize, LOG_SMEM);

    k_transpose<<<dim3(16, 32, 4), dim3(32, 8)>>>(z);               // 1 (+init)
    k_xp<<<16, 256>>>(Wp, bp);                                      // 2
    k_proj_mma<<<dim3(4, 32, 3), 256, PROJ_SMEM>>>(codebook, Wq, bq, Wk, bk, Wv, bv); // 3
    k_norms<<<V_ + MFULL + MREST, 512>>>(gq, gk);                   // 4 (profiled)
    k_logits_mma<<<dim3(V_/128, MTOT/128), 256, LOG_SMEM>>>();      // 5
    k_select<<<MTOT, 256>>>();                                      // 6
    k_out<<<8193, 256>>>(out);                                      // 7
}